// round 4
// baseline (speedup 1.0000x reference)
#include <cuda_runtime.h>

// NeuralCRF log-partition backward DP, one CTA per batch (B=64), T=128.
// Unnormalized-state formulation: v_i = exp(Beta_i - M).
//   step: u_j = v_j * exp(em_j) * r   (r = rcp(v0 from 2 executed steps ago))
//         v_i = sum_j exp(trans_ij) * u_j          <-- pure fp32 matvec
//         M  += log(v0)  (Kahan, identical in all threads, off critical path)
// No log/exp on the serial critical path: exp(em) is computed at prefetch
// time (2 rows early), rcp/log of the broadcast v0 run in the FMA shadow.
// Lag-2 renormalization telescopes, keeping |log v| bounded (~±25): fp32-safe.
// Exact block logsumexp only at the very end.

#define TDIM 128

typedef unsigned long long ull;

__device__ __forceinline__ ull pk2(float a, float b) {
    ull r; asm("mov.b64 %0, {%1,%2};" : "=l"(r) : "f"(a), "f"(b)); return r;
}
__device__ __forceinline__ void upk2(float& a, float& b, ull v) {
    asm("mov.b64 {%0,%1}, %2;" : "=f"(a), "=f"(b) : "l"(v));
}
__device__ __forceinline__ void fma2(ull& acc, ull a, ull b) {
    asm("fma.rn.f32x2 %0, %1, %2, %0;" : "+l"(acc) : "l"(a), "l"(b));
}
__device__ __forceinline__ void add2(ull& acc, ull a) {
    asm("add.rn.f32x2 %0, %0, %1;" : "+l"(acc) : "l"(a));
}
__device__ __forceinline__ float rcpf(float x) {
    float y; asm("rcp.approx.f32 %0, %1;" : "=f"(y) : "f"(x)); return y;
}

__global__ __launch_bounds__(TDIM, 1)
void crf_logz_kernel(const int* __restrict__ W,
                     const float* __restrict__ em,
                     const float* __restrict__ trans,
                     float* __restrict__ out,
                     int S)
{
    const int b = blockIdx.x;
    const int i = threadIdx.x;

    __shared__ __align__(16) float u_sm[2][TDIM];
    __shared__ float v0_sm[2];
    __shared__ float red_sm[8];

    // ---- E row i = exp(trans[i,:]) packed into 64 x f32x2 registers ----
    ull e2[TDIM / 2];
    {
        const float4* trow = reinterpret_cast<const float4*>(trans + i * TDIM);
#pragma unroll
        for (int j4 = 0; j4 < TDIM / 4; ++j4) {
            float4 t4 = __ldg(trow + j4);
            e2[2 * j4 + 0] = pk2(__expf(t4.x), __expf(t4.y));
            e2[2 * j4 + 1] = pk2(__expf(t4.z), __expf(t4.w));
        }
    }
    const float trans_bot = __ldg(trans + 1 * TDIM + i);  // trans[BOT_IDX=1, i]

    const float* emb = em + (size_t)b * (size_t)S * TDIM;
    const int*   Wb  = W  + (size_t)b * (size_t)S;

    float v  = 1.0f;                 // exp(Beta_i - M), Beta=0, M=0
    float r  = 1.0f, lg = 0.0f;      // renormalizer + its log (for M)
    float M  = 0.0f, Mc = 0.0f;      // Kahan-accumulated shift

    if (i == 0) { v0_sm[0] = 1.0f; v0_sm[1] = 1.0f; }

    // distance-2 prefetch of emission row (+ its exp) and word id
    float eA = emb[(size_t)(S - 1) * TDIM + i];
    float eB = emb[(size_t)(S - 2) * TDIM + i];
    float exA = __expf(eA);
    float exB = __expf(eB);
    int   wA = Wb[S - 1];
    int   wB = Wb[S - 2];

    int p = 0;  // parity over EXECUTED steps
    __syncthreads();

    for (int rr = S - 1; rr >= 1; --rr) {
        int rp = rr - 2;
        rp = rp < 0 ? 0 : rp;                // rr==1 prefetches row 0 (final)
        float eC = emb[(size_t)rp * TDIM + i];
        int   wC = Wb[rp];
        float exC = __expf(eC);              // off critical path (2 rows early)

        if ((wA != 0) & (wA != 3)) {         // mask, uniform across block
            u_sm[p][i] = v * (exA * r);      // 2 FMULs -> STS
            __syncthreads();                 // the ONLY barrier per step

            float v0read = v0_sm[1 - p];     // broadcast; published just now

            ull acc[8];
#pragma unroll
            for (int k = 0; k < 8; ++k) acc[k] = 0ull;

            const ulonglong2* u2p =
                reinterpret_cast<const ulonglong2*>(u_sm[p]);
#pragma unroll
            for (int k = 0; k < TDIM / 4; ++k) {   // 32 x LDS.128 broadcast
                ulonglong2 uv = u2p[k];
                fma2(acc[(2 * k)     & 7], e2[2 * k],     uv.x);
                fma2(acc[(2 * k + 1) & 7], e2[2 * k + 1], uv.y);
            }
            add2(acc[0], acc[4]);
            add2(acc[1], acc[5]);
            add2(acc[2], acc[6]);
            add2(acc[3], acc[7]);
            add2(acc[0], acc[2]);
            add2(acc[1], acc[3]);
            add2(acc[0], acc[1]);
            float s0, s1;
            upk2(s0, s1, acc[0]);
            v = s0 + s1;                      // new state; NO log on the path

            if (i == 0) v0_sm[p] = v;         // consumed 2 executed steps later

            // ---- shadow work (off the serial chain) ----
            {   // M += lg (Kahan); lg pairs with the r we just APPLIED
                float y = lg - Mc;
                float t = M + y;
                Mc = (t - M) - y;
                M = t;
            }
            r  = rcpf(v0read);                // for the NEXT executed step
            lg = __logf(v0read);
            p ^= 1;
        }

        eA = eB;  exA = exB;  wA = wB;
        eB = eC;  exB = exC;  wB = wC;
    }

    // ---- logZ = M + lse_i( trans[BOT,i] + em[b,0,i] + log v_i ), exact ----
    float f = trans_bot + eA + __logf(v);

    float mv = f;
#pragma unroll
    for (int o = 16; o > 0; o >>= 1)
        mv = fmaxf(mv, __shfl_xor_sync(0xffffffffu, mv, o));
    if ((i & 31) == 0) red_sm[i >> 5] = mv;
    __syncthreads();
    float mm = fmaxf(fmaxf(red_sm[0], red_sm[1]), fmaxf(red_sm[2], red_sm[3]));

    float s = __expf(f - mm);
#pragma unroll
    for (int o = 16; o > 0; o >>= 1)
        s += __shfl_xor_sync(0xffffffffu, s, o);
    if ((i & 31) == 0) red_sm[4 + (i >> 5)] = s;
    __syncthreads();

    if (i == 0) {
        float tot = (red_sm[4] + red_sm[5]) + (red_sm[6] + red_sm[7]);
        out[b] = M + mm + __logf(tot);
    }
}

extern "C" void kernel_launch(void* const* d_in, const int* in_sizes, int n_in,
                              void* d_out, int out_size)
{
    const int*   W     = (const int*)d_in[0];
    const float* em    = (const float*)d_in[1];
    const float* trans = (const float*)d_in[2];
    float*       out   = (float*)d_out;

    const int B = out_size;            // 64
    const int S = in_sizes[0] / B;     // 1024

    crf_logz_kernel<<<B, TDIM>>>(W, em, trans, out, S);
}